// round 9
// baseline (speedup 1.0000x reference)
#include <cuda_runtime.h>
#include <cstdint>

// Dense 2D spatial transformer (bilinear warp, zero-padded border).
// R8: exact R5 gather form (scalar LDGs, interior fast path, no branches in the
// hot loop) scaled to 8 pixels / 32 batched gathers per thread for deeper MLP.
//
// input1: [1,1,4096,4096] f32 image
// input2: [1,2,4096,4096] f32 flow (plane 0 = dH, plane 1 = dW)
// out:    [1,1,4096,4096] f32
//
// Reference semantics (padded coords in [0,4097], zero border):
//   H_up = flow_h + h + 1 ; W_up = flow_w + w + 1
//   hf = clip(floor(H_up),0,4097); hc = clip(hf+1,0,4097); same for w
//   dH = hc - H_up; dW = wc - W_up   (weights from CLIPPED coords)
//   out = v00*dW*dH + v10*dW*(1-dH) + v01*(1-dW)*dH + v11*(1-dW)*(1-dH)

#define H_DIM 4096
#define W_DIM 4096
#define HP_MAX 4097
#define PPT 8   // pixels per thread

__device__ __forceinline__ float fetch_padded(const float* __restrict__ img, int h, int w) {
    bool in = ((unsigned)(h - 1) < (unsigned)H_DIM) & ((unsigned)(w - 1) < (unsigned)W_DIM);
    int idx = ((h - 1) << 12) + (w - 1);
    return in ? __ldg(img + idx) : 0.0f;
}

__global__ void __launch_bounds__(256, 3)
dense_warp_kernel(const float* __restrict__ img,
                  const float* __restrict__ flowH,
                  const float* __restrict__ flowW,
                  float* __restrict__ out) {
    int t = blockIdx.x * blockDim.x + threadIdx.x;
    int base = t * PPT;                      // 8 consecutive pixels, same row
                                             // (W=4096 divisible by 8 -> no row straddle)
    float fhv[PPT], fwv[PPT];
    {
        float4 a = *reinterpret_cast<const float4*>(flowH + base);
        float4 b = *reinterpret_cast<const float4*>(flowH + base + 4);
        fhv[0]=a.x; fhv[1]=a.y; fhv[2]=a.z; fhv[3]=a.w;
        fhv[4]=b.x; fhv[5]=b.y; fhv[6]=b.z; fhv[7]=b.w;
        float4 c = *reinterpret_cast<const float4*>(flowW + base);
        float4 d = *reinterpret_cast<const float4*>(flowW + base + 4);
        fwv[0]=c.x; fwv[1]=c.y; fwv[2]=c.z; fwv[3]=c.w;
        fwv[4]=d.x; fwv[5]=d.y; fwv[6]=d.z; fwv[7]=d.w;
    }

    int h = base >> 12;
    int w = base & (W_DIM - 1);

    const float hp1 = (float)(h + 1);
    const float wp1 = (float)(w + 1);

    float v00[PPT], v01[PPT], v10[PPT], v11[PPT];
    float dH[PPT], dW[PPT];

    // ---- phase 1: indices + issue all 32 gathers ----
    #pragma unroll
    for (int k = 0; k < PPT; k++) {
        float Hu = fhv[k] + hp1;
        float Wu = fwv[k] + wp1 + (float)k;

        float fhf = floorf(Hu);
        float fwf = floorf(Wu);
        int hf = (int)fhf;
        int wf = (int)fwf;

        if (((unsigned)(hf - 1) <= 4094u) & ((unsigned)(wf - 1) <= 4094u)) {
            // interior fast path: one base index, immediate offsets
            dH[k] = (fhf + 1.0f) - Hu;
            dW[k] = (fwf + 1.0f) - Wu;
            int idx = (hf << 12) + wf - (W_DIM + 1);   // (hf-1)*4096 + (wf-1)
            v00[k] = __ldg(img + idx);
            v01[k] = __ldg(img + idx + 1);
            v10[k] = __ldg(img + idx + W_DIM);
            v11[k] = __ldg(img + idx + W_DIM + 1);
        } else {
            int hc = hf + 1, wc = wf + 1;
            int hfc = min(max(hf, 0), HP_MAX);
            int hcc = min(max(hc, 0), HP_MAX);
            int wfc = min(max(wf, 0), HP_MAX);
            int wcc = min(max(wc, 0), HP_MAX);
            dH[k] = (float)hcc - Hu;
            dW[k] = (float)wcc - Wu;
            v00[k] = fetch_padded(img, hfc, wfc);
            v01[k] = fetch_padded(img, hfc, wcc);
            v10[k] = fetch_padded(img, hcc, wfc);
            v11[k] = fetch_padded(img, hcc, wcc);
        }
    }

    // ---- phase 2: pure-FMA combine ----
    float o[PPT];
    #pragma unroll
    for (int k = 0; k < PPT; k++) {
        float eH = 1.0f - dH[k];
        float eW = 1.0f - dW[k];
        float a = fmaf(eW, v01[k], dW[k] * v00[k]);
        float b = fmaf(eW, v11[k], dW[k] * v10[k]);
        o[k] = fmaf(eH, b, dH[k] * a);
    }

    *reinterpret_cast<float4*>(out + base)     = make_float4(o[0], o[1], o[2], o[3]);
    *reinterpret_cast<float4*>(out + base + 4) = make_float4(o[4], o[5], o[6], o[7]);
}

extern "C" void kernel_launch(void* const* d_in, const int* in_sizes, int n_in,
                              void* d_out, int out_size) {
    const float* img   = (const float*)d_in[0];
    const float* flowH = (const float*)d_in[1];
    const float* flowW = (const float*)d_in[1] + (size_t)H_DIM * W_DIM;
    float* out = (float*)d_out;

    const int n_pix = H_DIM * W_DIM;
    const int threads = 256;
    const int blocks = (n_pix / PPT) / threads;   // 8192
    dense_warp_kernel<<<blocks, threads>>>(img, flowH, flowW, out);
}

// round 10
// speedup vs baseline: 1.3811x; 1.3811x over previous
#include <cuda_runtime.h>
#include <cstdint>

// Dense 2D spatial transformer (bilinear warp, zero-padded border).
// R9: vertical-strip layout. Each thread owns 1 column x 4 rows; a warp covers
// 32 consecutive columns x 4 rows, so every gather instruction's footprint
// spans only ~128B of columns (minimal distinct sectors). Flow loads and
// output stores are coalesced scalar accesses at immediate offsets k*4096.
// Keeps R5's interior fast path + batched 16-gather MLP.
//
// input1: [1,1,4096,4096] f32 image
// input2: [1,2,4096,4096] f32 flow (plane 0 = dH, plane 1 = dW)
// out:    [1,1,4096,4096] f32
//
// Reference semantics (padded coords in [0,4097], zero border):
//   H_up = flow_h + h + 1 ; W_up = flow_w + w + 1
//   hf = clip(floor(H_up),0,4097); hc = clip(hf+1,0,4097); same for w
//   dH = hc - H_up; dW = wc - W_up   (weights from CLIPPED coords)
//   out = v00*dW*dH + v10*dW*(1-dH) + v01*(1-dW)*dH + v11*(1-dW)*(1-dH)

#define H_DIM 4096
#define W_DIM 4096
#define HP_MAX 4097
#define RPT 4   // rows per thread

__device__ __forceinline__ float fetch_padded(const float* __restrict__ img, int h, int w) {
    bool in = ((unsigned)(h - 1) < (unsigned)H_DIM) & ((unsigned)(w - 1) < (unsigned)W_DIM);
    int idx = ((h - 1) << 12) + (w - 1);
    return in ? __ldg(img + idx) : 0.0f;
}

__global__ void __launch_bounds__(256, 4)
dense_warp_kernel(const float* __restrict__ img,
                  const float* __restrict__ flowH,
                  const float* __restrict__ flowW,
                  float* __restrict__ out) {
    // block tile: 256 columns x 4 rows; thread strip: 1 column x 4 rows
    const int w  = (blockIdx.x << 8) + threadIdx.x;
    const int h0 = blockIdx.y << 2;
    const int base = (h0 << 12) + w;         // element index of (h0, w)

    // flow loads: coalesced scalars at immediate offsets k*4096
    float fhv[RPT], fwv[RPT];
    #pragma unroll
    for (int k = 0; k < RPT; k++) {
        fhv[k] = __ldg(flowH + base + (k << 12));
        fwv[k] = __ldg(flowW + base + (k << 12));
    }

    const float wp1 = (float)(w + 1);
    const float hp1 = (float)(h0 + 1);

    float v00[RPT], v01[RPT], v10[RPT], v11[RPT];
    float dH[RPT], dW[RPT];

    // ---- phase 1: indices + issue all 16 gathers ----
    #pragma unroll
    for (int k = 0; k < RPT; k++) {
        float Hu = fhv[k] + hp1 + (float)k;
        float Wu = fwv[k] + wp1;

        float fhf = floorf(Hu);
        float fwf = floorf(Wu);
        int hf = (int)fhf;
        int wf = (int)fwf;

        if (((unsigned)(hf - 1) <= 4094u) & ((unsigned)(wf - 1) <= 4094u)) {
            // interior fast path: one base index, immediate offsets
            dH[k] = (fhf + 1.0f) - Hu;
            dW[k] = (fwf + 1.0f) - Wu;
            int idx = (hf << 12) + wf - (W_DIM + 1);   // (hf-1)*4096 + (wf-1)
            v00[k] = __ldg(img + idx);
            v01[k] = __ldg(img + idx + 1);
            v10[k] = __ldg(img + idx + W_DIM);
            v11[k] = __ldg(img + idx + W_DIM + 1);
        } else {
            int hc = hf + 1, wc = wf + 1;
            int hfc = min(max(hf, 0), HP_MAX);
            int hcc = min(max(hc, 0), HP_MAX);
            int wfc = min(max(wf, 0), HP_MAX);
            int wcc = min(max(wc, 0), HP_MAX);
            dH[k] = (float)hcc - Hu;
            dW[k] = (float)wcc - Wu;
            v00[k] = fetch_padded(img, hfc, wfc);
            v01[k] = fetch_padded(img, hfc, wcc);
            v10[k] = fetch_padded(img, hcc, wfc);
            v11[k] = fetch_padded(img, hcc, wcc);
        }
    }

    // ---- phase 2: pure-FMA combine + coalesced scalar stores ----
    #pragma unroll
    for (int k = 0; k < RPT; k++) {
        float eH = 1.0f - dH[k];
        float eW = 1.0f - dW[k];
        float a = fmaf(eW, v01[k], dW[k] * v00[k]);
        float b = fmaf(eW, v11[k], dW[k] * v10[k]);
        out[base + (k << 12)] = fmaf(eH, b, dH[k] * a);
    }
}

extern "C" void kernel_launch(void* const* d_in, const int* in_sizes, int n_in,
                              void* d_out, int out_size) {
    const float* img   = (const float*)d_in[0];
    const float* flowH = (const float*)d_in[1];
    const float* flowW = (const float*)d_in[1] + (size_t)H_DIM * W_DIM;
    float* out = (float*)d_out;

    dim3 grid(W_DIM / 256, H_DIM / RPT);   // 16 x 1024 = 16384 blocks
    dense_warp_kernel<<<grid, 256>>>(img, flowH, flowW, out);
}

// round 11
// speedup vs baseline: 1.4284x; 1.0343x over previous
#include <cuda_runtime.h>
#include <cstdint>

// Dense 2D spatial transformer (bilinear warp, zero-padded border).
// R10: vertical strip deepened to 8 rows/thread. Warp gather footprint stays
// 32 consecutive columns (minimal sectors/instruction, per R9), while batched
// per-thread MLP doubles to 32 gathers + 16 flow loads for latency hiding.
//
// input1: [1,1,4096,4096] f32 image
// input2: [1,2,4096,4096] f32 flow (plane 0 = dH, plane 1 = dW)
// out:    [1,1,4096,4096] f32
//
// Reference semantics (padded coords in [0,4097], zero border):
//   H_up = flow_h + h + 1 ; W_up = flow_w + w + 1
//   hf = clip(floor(H_up),0,4097); hc = clip(hf+1,0,4097); same for w
//   dH = hc - H_up; dW = wc - W_up   (weights from CLIPPED coords)
//   out = v00*dW*dH + v10*dW*(1-dH) + v01*(1-dW)*dH + v11*(1-dW)*(1-dH)

#define H_DIM 4096
#define W_DIM 4096
#define HP_MAX 4097
#define RPT 8   // rows per thread

__device__ __forceinline__ float fetch_padded(const float* __restrict__ img, int h, int w) {
    bool in = ((unsigned)(h - 1) < (unsigned)H_DIM) & ((unsigned)(w - 1) < (unsigned)W_DIM);
    int idx = ((h - 1) << 12) + (w - 1);
    return in ? __ldg(img + idx) : 0.0f;
}

__global__ void __launch_bounds__(256, 3)
dense_warp_kernel(const float* __restrict__ img,
                  const float* __restrict__ flowH,
                  const float* __restrict__ flowW,
                  float* __restrict__ out) {
    // block tile: 256 columns x 8 rows; thread strip: 1 column x 8 rows
    const int w  = (blockIdx.x << 8) + threadIdx.x;
    const int h0 = blockIdx.y << 3;
    const int base = (h0 << 12) + w;         // element index of (h0, w)

    // flow loads: coalesced scalars at immediate offsets k*4096 (16 loads batched)
    float fhv[RPT], fwv[RPT];
    #pragma unroll
    for (int k = 0; k < RPT; k++) {
        fhv[k] = __ldg(flowH + base + (k << 12));
        fwv[k] = __ldg(flowW + base + (k << 12));
    }

    const float wp1 = (float)(w + 1);
    const float hp1 = (float)(h0 + 1);

    float v00[RPT], v01[RPT], v10[RPT], v11[RPT];
    float dH[RPT], dW[RPT];

    // ---- phase 1: indices + issue all 32 gathers ----
    #pragma unroll
    for (int k = 0; k < RPT; k++) {
        float Hu = fhv[k] + hp1 + (float)k;
        float Wu = fwv[k] + wp1;

        float fhf = floorf(Hu);
        float fwf = floorf(Wu);
        int hf = (int)fhf;
        int wf = (int)fwf;

        if (((unsigned)(hf - 1) <= 4094u) & ((unsigned)(wf - 1) <= 4094u)) {
            // interior fast path: one base index, immediate offsets
            dH[k] = (fhf + 1.0f) - Hu;
            dW[k] = (fwf + 1.0f) - Wu;
            int idx = (hf << 12) + wf - (W_DIM + 1);   // (hf-1)*4096 + (wf-1)
            v00[k] = __ldg(img + idx);
            v01[k] = __ldg(img + idx + 1);
            v10[k] = __ldg(img + idx + W_DIM);
            v11[k] = __ldg(img + idx + W_DIM + 1);
        } else {
            int hc = hf + 1, wc = wf + 1;
            int hfc = min(max(hf, 0), HP_MAX);
            int hcc = min(max(hc, 0), HP_MAX);
            int wfc = min(max(wf, 0), HP_MAX);
            int wcc = min(max(wc, 0), HP_MAX);
            dH[k] = (float)hcc - Hu;
            dW[k] = (float)wcc - Wu;
            v00[k] = fetch_padded(img, hfc, wfc);
            v01[k] = fetch_padded(img, hfc, wcc);
            v10[k] = fetch_padded(img, hcc, wfc);
            v11[k] = fetch_padded(img, hcc, wcc);
        }
    }

    // ---- phase 2: pure-FMA combine + coalesced scalar stores ----
    #pragma unroll
    for (int k = 0; k < RPT; k++) {
        float eH = 1.0f - dH[k];
        float eW = 1.0f - dW[k];
        float a = fmaf(eW, v01[k], dW[k] * v00[k]);
        float b = fmaf(eW, v11[k], dW[k] * v10[k]);
        out[base + (k << 12)] = fmaf(eH, b, dH[k] * a);
    }
}

extern "C" void kernel_launch(void* const* d_in, const int* in_sizes, int n_in,
                              void* d_out, int out_size) {
    const float* img   = (const float*)d_in[0];
    const float* flowH = (const float*)d_in[1];
    const float* flowW = (const float*)d_in[1] + (size_t)H_DIM * W_DIM;
    float* out = (float*)d_out;

    dim3 grid(W_DIM / 256, H_DIM / RPT);   // 16 x 512 = 8192 blocks
    dense_warp_kernel<<<grid, 256>>>(img, flowH, flowW, out);
}